// round 8
// baseline (speedup 1.0000x reference)
#include <cuda_runtime.h>
#include <cstdint>

typedef unsigned long long u64;

#define BATCH 32
#define HID   64
#define CHUNK 2048
#define LOGC  11

__device__ __forceinline__ u64 fma2(u64 a, u64 b, u64 c){
    u64 d; asm("fma.rn.f32x2 %0, %1, %2, %3;" : "=l"(d) : "l"(a), "l"(b), "l"(c)); return d;
}
__device__ __forceinline__ u64 add2(u64 a, u64 b){
    u64 d; asm("add.rn.f32x2 %0, %1, %2;" : "=l"(d) : "l"(a), "l"(b)); return d;
}
__device__ __forceinline__ float hsum2(u64 a){
    float lo, hi; asm("mov.b64 {%0,%1}, %2;" : "=f"(lo), "=f"(hi) : "l"(a)); return lo + hi;
}
__device__ __forceinline__ float ex2f(float a){
    float d; asm("ex2.approx.f32 %0, %1;" : "=f"(d) : "f"(a)); return d;
}
__device__ __forceinline__ float rcpf(float a){
    float d; asm("rcp.approx.f32 %0, %1;" : "=f"(d) : "f"(a)); return d;
}

#define NEG_L2E (-1.4426950408889634f)
#define TWO_L2E  2.8853900817779268f

// One CTA per batch row. 128 threads; pair (2i,2i+1) owns hidden unit i.
// j-SPLIT decomposition: lane p owns h[32p:32p+32) and computes r/z/n
// PARTIALS over its half (48 FMA2, 8 LDS.128 per thread -- half the issue
// of the gate-split scheme). 3 shfl_xor(1) complete the dots on both lanes;
// both lanes run the sigma/tanh tail redundantly (thread-local); lane p=0
// stores h and states. ex2 args fused; branch-free inner loop; h ping-pong.
__global__ void __launch_bounds__(128, 1)
gru_kernel(const float* __restrict__ x, const float* __restrict__ w_ih,
           const float* __restrict__ w_hh, const float* __restrict__ b_ih,
           const float* __restrict__ b_hh, float* __restrict__ states, int T)
{
    __shared__ __align__(16) float hbuf[2][HID];
    __shared__ __align__(16) float xs[2][CHUNK];

    const int tid = threadIdx.x;
    const int b   = blockIdx.x;
    const int i   = tid >> 1;
    const int p   = tid & 1;
    const int jo  = 32 * p;            // h-half offset owned by this lane

    // weight slices: rows i (r), 64+i (z), 128+i (n); 32 floats from col jo
    u64 wr[16], wz[16], wn[16];
    {
        const u64* s0 = (const u64*)(w_hh + (size_t)i * 64 + jo);
        const u64* s1 = (const u64*)(w_hh + (size_t)(64 + i) * 64 + jo);
        const u64* s2 = (const u64*)(w_hh + (size_t)(128 + i) * 64 + jo);
        #pragma unroll
        for (int q = 0; q < 16; q++) { wr[q] = s0[q]; wz[q] = s1[q]; wn[q] = s2[q]; }
    }

    // fused activation constants (per-unit; both lanes carry r AND z consts)
    const float wihrL = w_ih[i] * NEG_L2E;
    const float carL  = (b_hh[i] + b_ih[i]) * NEG_L2E;
    const float wihzL = w_ih[64 + i] * NEG_L2E;
    const float cazL  = (b_hh[64 + i] + b_ih[64 + i]) * NEG_L2E;
    const float wihn2 = w_ih[128 + i] * TWO_L2E;
    const float bihn2 = b_ih[128 + i] * TWO_L2E;
    const float bhhn2 = b_hh[128 + i] * TWO_L2E;

    const float* xrow = x + (size_t)b * T;

    if (tid < HID) hbuf[0][tid] = 0.0f;
    {
        const float4* src = (const float4*)xrow;
        float4* dst = (float4*)xs[0];
        #pragma unroll
        for (int q = 0; q < CHUNK / 4 / 128; q++) dst[tid + q * 128] = src[tid + q * 128];
    }
    __syncthreads();

    float* sout = states + ((size_t)b * T) * HID + i;
    float hprev = 0.0f;
    const int nch = T >> LOGC;

    auto step = [&](const float* hc, float* hd, float xt, float* sp) {
        const float xrc = fmaf(xt, wihrL, carL);
        const float xzc = fmaf(xt, wihzL, cazL);
        const float xn2 = fmaf(xt, wihn2, bihn2);

        // load my h-half once (8 x LDS.128, 2-address broadcast per instr)
        ulonglong2 hv[8];
        const ulonglong2* hs = (const ulonglong2*)(hc + jo);
        #pragma unroll
        for (int q = 0; q < 8; q++) hv[q] = hs[q];

        // r-partial over my half (16 FMA2)
        u64 r0=0,r1=0,r2=0,r3=0;
        #pragma unroll
        for (int q = 0; q < 4; q++) {
            r0 = fma2(hv[2*q].x,   wr[4*q],   r0);
            r1 = fma2(hv[2*q].y,   wr[4*q+1], r1);
            r2 = fma2(hv[2*q+1].x, wr[4*q+2], r2);
            r3 = fma2(hv[2*q+1].y, wr[4*q+3], r3);
        }
        float rp = hsum2(add2(add2(r0,r1), add2(r2,r3)));
        float sr = rp + __shfl_xor_sync(0xffffffffu, rp, 1);
        float gr = rcpf(1.0f + ex2f(fmaf(sr, NEG_L2E, xrc)));  // sigma(r)

        // z-partial (16 FMA2) -- issues under the sigma(r) chain
        u64 z0=0,z1=0,z2=0,z3=0;
        #pragma unroll
        for (int q = 0; q < 4; q++) {
            z0 = fma2(hv[2*q].x,   wz[4*q],   z0);
            z1 = fma2(hv[2*q].y,   wz[4*q+1], z1);
            z2 = fma2(hv[2*q+1].x, wz[4*q+2], z2);
            z3 = fma2(hv[2*q+1].y, wz[4*q+3], z3);
        }
        float zp = hsum2(add2(add2(z0,z1), add2(z2,z3)));
        float sz = zp + __shfl_xor_sync(0xffffffffu, zp, 1);

        // n-partial (16 FMA2)
        u64 n0=0,n1=0,n2=0,n3=0;
        #pragma unroll
        for (int q = 0; q < 4; q++) {
            n0 = fma2(hv[2*q].x,   wn[4*q],   n0);
            n1 = fma2(hv[2*q].y,   wn[4*q+1], n1);
            n2 = fma2(hv[2*q+1].x, wn[4*q+2], n2);
            n3 = fma2(hv[2*q+1].y, wn[4*q+3], n3);
        }
        float np = hsum2(add2(add2(n0,n1), add2(n2,n3)));
        float sn = np + __shfl_xor_sync(0xffffffffu, np, 1);

        // tail (redundant on both lanes; thread-local)
        float gz  = rcpf(1.0f + ex2f(fmaf(sz, NEG_L2E, xzc)));   // sigma(z), slack
        float hn2 = fmaf(sn, TWO_L2E, bhhn2);
        float e2  = ex2f(fmaf(gr, hn2, xn2));
        float nv  = fmaf(-2.0f, rcpf(e2 + 1.0f), 1.0f);          // tanh
        float hnew = fmaf(gz, hprev - nv, nv);                   // (1-z)*n + z*h
        hprev = hnew;

        if (!p) {
            hd[i] = hnew;
            __stcs(sp, hnew);
        }
        __syncthreads();
    };

    for (int c = 0; c < nch; c++) {
        if (c + 1 < nch) {  // prefetch next x chunk: one branch per 2048 steps
            const float4* src = (const float4*)(xrow + (size_t)(c + 1) * CHUNK);
            float4* dst = (float4*)xs[(c + 1) & 1];
            #pragma unroll
            for (int q = 0; q < CHUNK / 4 / 128; q++) dst[tid + q * 128] = src[tid + q * 128];
        }
        const float* xc = xs[c & 1];
        float* sc = sout + (size_t)c * CHUNK * HID;

        for (int tl = 0; tl < CHUNK; tl += 2) {
            step(hbuf[0], hbuf[1], xc[tl],     sc + (size_t)tl * HID);
            step(hbuf[1], hbuf[0], xc[tl + 1], sc + (size_t)(tl + 1) * HID);
        }
    }
}

// out[n] = dot(states[n,:], w_lin) + b_lin + x[n]
#define HROWS 128
#define HPAD  65
__global__ void __launch_bounds__(128, 4)
head_kernel(const float* __restrict__ st, const float* __restrict__ x,
            const float* __restrict__ wl, const float* __restrict__ bl,
            float* __restrict__ out, int BT)
{
    __shared__ float tile[HROWS * HPAD];
    __shared__ float wsh[HID];

    const int tid = threadIdx.x;
    const size_t row0 = (size_t)blockIdx.x * HROWS;

    if (tid < HID) wsh[tid] = wl[tid];

    const float4* src = (const float4*)(st + row0 * HID);
    #pragma unroll
    for (int q = 0; q < (HROWS * HID / 4) / 128; q++) {
        int f4 = tid + q * 128;
        float4 v = src[f4];
        int flat = f4 * 4;
        int r = flat >> 6;
        int c = flat & 63;
        float* drow = &tile[r * HPAD + c];
        drow[0] = v.x; drow[1] = v.y; drow[2] = v.z; drow[3] = v.w;
    }
    __syncthreads();

    const float* trow = &tile[tid * HPAD];
    float acc = 0.0f;
    #pragma unroll
    for (int k = 0; k < HID; k++) acc = fmaf(trow[k], wsh[k], acc);

    size_t n = row0 + tid;
    out[n] = acc + bl[0] + x[n];
}

extern "C" void kernel_launch(void* const* d_in, const int* in_sizes, int n_in,
                              void* d_out, int out_size)
{
    const float* x     = (const float*)d_in[0];
    const float* w_ih  = (const float*)d_in[1];
    const float* w_hh  = (const float*)d_in[2];
    const float* b_ih  = (const float*)d_in[3];
    const float* b_hh  = (const float*)d_in[4];
    const float* w_lin = (const float*)d_in[5];
    const float* b_lin = (const float*)d_in[6];

    float* out = (float*)d_out;
    const int BT = in_sizes[0];          // B * T
    const int T  = BT / BATCH;
    float* states = out + BT;            // d_out = [out | states]

    gru_kernel<<<BATCH, 128>>>(x, w_ih, w_hh, b_ih, b_hh, states, T);
    head_kernel<<<BT / HROWS, 128>>>(states, x, w_lin, b_lin, out, BT);
}